// round 16
// baseline (speedup 1.0000x reference)
#include <cuda_runtime.h>
#include <cuda_fp16.h>
#include <cstdint>

// NRI MLPDecoder. L1 = mma.m16n8k8.tf32 (A-frags computed straight from XS),
// L2 = z^T = W2(A, ldsm) @ h1^T(B = L1 C-frags, in reg),
// agg = relu(z^T)(A in reg) @ R^T(B built per-lane in registers from RTk)
//       -> sparse atomicAdd into AGG.
// NO per-tile smem buffers, NO per-tile barriers (9 syncs total in phase A).
// 3 CTAs/SM (65KB smem, target <=84 regs).
// B=16,N=30,T=50(49 out),D=4,K=4,H=M=NH=128,E=870 (pad 896 = 7x128).
// One CTA = one (b,t), 256 threads, grid 784. Warp w owns edges w*16..w*16+15.

typedef unsigned long long ull;

#define NB 16
#define NN 30
#define TFULL 50
#define TOUT 49
#define EDGES 870
#define EPAD 896
#define NTILE 7
#define THREADS 256
#define GRID (NB*TOUT)

// ---------------- smem byte offsets ----------------
#define SW2   0          // W2^T k-slice fp16 [128 f][136 c] = 34816
#define SW1K  34816      // W1k tf32 [8][136] = 4352
#define SB1   39168      // b1 f32 [4][128] = 2048
#define SB2   41216      // b2 f32 [4][128] = 2048
#define SRTK  43264      // rt_k f32 [896] = 3584
#define SAGG  46848      // agg f32 [30][132] = 15840 (ends 62688)
#define SXS   63488      // x f32 [32][4] = 512
#define SOB   64000      // ob1 512 + ob2 512 + ob3 16 = 1040
#define SMEM_BYTES 65040

// phase-B aliases (phase-A regions dead; AGG consumed into AUG first)
#define PB_AUG  0            // [30][132] f32 = 15840
#define PB_H    16384        // [30][128] f32 = 15360
#define PB_P0   32768        // [30][128] f32 (over W1K/B1/B2/RTK/AGG-head, dead)
#define PB_P1   48128        // [30][128] f32 (ends 63488 = SXS, no clobber)
#define PB_H2   0            // [30][129] f32 (AUG dead by then)

__device__ __align__(16) __half g_W2h[4*128*136];  // W2^T fp16: [k][f][c_pad136]

// ---------------- helpers ----------------
__device__ __forceinline__ uint32_t smem_u32(const void* p){
  uint32_t a; asm("{ .reg .u64 t; cvta.to.shared.u64 t, %1; cvt.u32.u64 %0, t; }" : "=r"(a) : "l"(p));
  return a;
}
__device__ __forceinline__ void cp16(uint32_t dst, const void* src){
  asm volatile("cp.async.ca.shared.global [%0], [%1], 16;" :: "r"(dst), "l"(src));
}
__device__ __forceinline__ void cp_commit(){ asm volatile("cp.async.commit_group;" ::: "memory"); }
__device__ __forceinline__ void cp_wait0(){ asm volatile("cp.async.wait_group 0;" ::: "memory"); }
__device__ __forceinline__ float cvt_tf32(float x){
  float o; asm("cvt.rna.tf32.f32 %0, %1;" : "=f"(o) : "f"(x)); return o;
}
__device__ __forceinline__ void mma16816(float* c,
    uint32_t a0, uint32_t a1, uint32_t a2, uint32_t a3,
    uint32_t b0, uint32_t b1){
  asm volatile("mma.sync.aligned.m16n8k16.row.col.f32.f16.f16.f32 "
    "{%0,%1,%2,%3}, {%4,%5,%6,%7}, {%8,%9}, {%0,%1,%2,%3};"
    : "+f"(c[0]), "+f"(c[1]), "+f"(c[2]), "+f"(c[3])
    : "r"(a0), "r"(a1), "r"(a2), "r"(a3), "r"(b0), "r"(b1));
}
__device__ __forceinline__ void mma_tf32(float* c,
    const uint32_t* a, uint32_t b0, uint32_t b1){
  asm volatile("mma.sync.aligned.m16n8k8.row.col.f32.tf32.tf32.f32 "
    "{%0,%1,%2,%3}, {%4,%5,%6,%7}, {%8,%9}, {%0,%1,%2,%3};"
    : "+f"(c[0]), "+f"(c[1]), "+f"(c[2]), "+f"(c[3])
    : "r"(a[0]), "r"(a[1]), "r"(a[2]), "r"(a[3]), "r"(b0), "r"(b1));
}
__device__ __forceinline__ void ldsm4(uint32_t* r, uint32_t addr){
  asm volatile("ldmatrix.sync.aligned.m8n8.x4.shared.b16 {%0,%1,%2,%3}, [%4];"
    : "=r"(r[0]), "=r"(r[1]), "=r"(r[2]), "=r"(r[3]) : "r"(addr));
}
__device__ __forceinline__ uint32_t relu_pack(float a, float b){
  __half2 h = __floats2half2_rn(a, b);
  __half2 z = __half2half2(__ushort_as_half(0));
  __half2 r = __hmax2(h, z);
  return *(uint32_t*)&r;
}
__device__ __forceinline__ uint32_t pack_h2(float a, float b){
  __half2 h = __floats2half2_rn(a, b);
  return *(uint32_t*)&h;
}

// ---------------- prep: W2^T -> fp16, padded stride 136 ----------------
__global__ void prep_w2(const float* __restrict__ W2){
  int idx = blockIdx.x * blockDim.x + threadIdx.x;
  if (idx >= 4*128*128) return;
  int k = idx >> 14, rem = idx & 16383;
  int m = rem >> 7, c = rem & 127;
  g_W2h[(k*128 + m)*136 + c] = __float2half(W2[(k*128 + c)*128 + m]);
}

// ---------------- main ----------------
extern __shared__ __align__(16) char smc[];

__global__ __launch_bounds__(THREADS, 3)
void nri_mma_kernel(
    const float* __restrict__ inputs,    // [16,30,50,4]
    const float* __restrict__ rel_type,  // [16,870,4]
    const float* __restrict__ W1,        // [4,8,128]
    const float* __restrict__ b1,        // [4,128]
    const float* __restrict__ b2,        // [4,128]
    const float* __restrict__ oW1,       // [132,128]
    const float* __restrict__ ob1,
    const float* __restrict__ oW2,       // [128,128]
    const float* __restrict__ ob2,
    const float* __restrict__ oW3,       // [128,4]
    const float* __restrict__ ob3,
    float* __restrict__ out)             // [16,30,49,4]
{
  const int tid  = threadIdx.x;
  const int lane = tid & 31;
  const int g    = lane >> 2;
  const int tg   = lane & 3;
  const int wid  = tid >> 5;       // warp owns tile edges wid*16..wid*16+15
  const int b = blockIdx.x / TOUT;
  const int t = blockIdx.x % TOUT;

  const uint32_t sbase = smem_u32(smc);
  float* W1Ks = (float*)(smc + SW1K);
  float* b1s  = (float*)(smc + SB1);
  float* b2s  = (float*)(smc + SB2);
  float* RTk  = (float*)(smc + SRTK);
  float* AGG  = (float*)(smc + SAGG);
  float* XS   = (float*)(smc + SXS);
  float* ob1s = (float*)(smc + SOB);
  float* ob2s = (float*)(smc + SOB + 512);
  float* ob3s = (float*)(smc + SOB + 1024);

  // ---- prologue ----
  for (int i = tid; i < 128; i += THREADS){
    cp16(sbase + SB1 + i*16, (const char*)b1 + i*16);
    cp16(sbase + SB2 + i*16, (const char*)b2 + i*16);
  }
  cp_commit();
  if (tid < 120){
    int n = tid >> 2, d = tid & 3;
    XS[tid] = inputs[((b*NN + n)*TFULL + t)*4 + d];
  }
  for (int i = tid; i < NN*132; i += THREADS) AGG[i] = 0.f;
  if (tid < 128) ob1s[tid] = ob1[tid];
  else           ob2s[tid-128] = ob2[tid-128];
  if (tid < 4) ob3s[tid] = ob3[tid];
  cp_wait0();

  // ================= relation types (outer) =================
  for (int k = 0; k < 4; k++){
    // ---- stage W2k (fp16), W1k (tf32), rt_k ----
    for (int i = tid; i < 2176; i += THREADS)
      cp16(sbase + SW2 + i*16, (const char*)g_W2h + k*34816 + i*16);
    cp_commit();
    for (int i = tid; i < 1024; i += THREADS)
      W1Ks[(i >> 7)*136 + (i & 127)] = cvt_tf32(W1[k*1024 + i]);
    for (int i = tid; i < EPAD; i += THREADS)
      RTk[i] = (i < EDGES) ? rel_type[(b*EDGES + i)*4 + k] : 0.f;
    cp_wait0();
    __syncthreads();     // staged data visible; also covers prologue on k=0

    const float* b1k = b1s + k*128;
    const float* b2k = b2s + k*128;
    const uint32_t wbase = sbase + SW2 + (uint32_t)((lane & 15)*272 + (lane >> 4)*16);

    // ---- edge tiles of 128 (NO intra-tile barriers) ----
    for (int m = 0; m < NTILE; m++){
      const int gbase = m*128;
      const int n0 = (gbase*565) >> 14;
      const int we = gbase + wid*16;

      // ---- per-lane node flags + row pointers ----
      int tch = 0;
      float* prow[4];
      #pragma unroll
      for (int ii = 0; ii < 4; ii++){
        const int nd = (ii >> 1)*8 + tg*2 + (ii & 1);
        const int row = n0 + nd;
        const int rc = (row < NN) ? row : 0;
        prow[ii] = AGG + rc*132 + g;
        const int er0 = row*29, er1 = er0 + 28;
        const bool tc = (row < NN) && (er1 >= we) && (er0 <= we + 15);
        tch |= ((int)tc) << ii;
      }

      // ---- R B-frags built directly in registers from RTk ----
      uint32_t bt[4];
      {
        const int e0 = we + tg*2;
        const float2 rt01 = *(const float2*)(RTk + e0);
        const float2 rt89 = *(const float2*)(RTk + e0 + 8);
        const int r0 = (e0*565) >> 14;
        const int r1 = ((e0+1)*565) >> 14;
        const int r8 = ((e0+8)*565) >> 14;
        const int r9 = ((e0+9)*565) >> 14;
        const int nlo = n0 + g, nhi = n0 + 8 + g;
        bt[0] = pack_h2(r0==nlo?rt01.x:0.f, r1==nlo?rt01.y:0.f);
        bt[1] = pack_h2(r8==nlo?rt89.x:0.f, r9==nlo?rt89.y:0.f);
        bt[2] = pack_h2(r0==nhi?rt01.x:0.f, r1==nhi?rt01.y:0.f);
        bt[3] = pack_h2(r8==nhi?rt89.x:0.f, r9==nhi?rt89.y:0.f);
      }

      // ---- layer-1 A-frags straight from XS (no PRE buffer) ----
      uint32_t za[4];
      {
        const int ea = we + g, eb = ea + 8;
        int na = 0, sa = 0, nb = 0, sb = 0;
        if (ea < EDGES){ na = (ea*565) >> 14; int ix = ea - na*29; sa = ix + (ix >= na); }
        if (eb < EDGES){ nb = (eb*565) >> 14; int ix = eb - nb*29; sb = ix + (ix >= nb); }
        za[0] = __float_as_uint(cvt_tf32(XS[na*4 + tg]));
        za[1] = __float_as_uint(cvt_tf32(XS[nb*4 + tg]));
        za[2] = __float_as_uint(cvt_tf32(XS[sa*4 + tg]));
        za[3] = __float_as_uint(cvt_tf32(XS[sb*4 + tg]));
      }

      // ---- layer 1: tf32 MMA -> relu -> fp16 frags (B-frags of L2) ----
      uint32_t af[8][4];
      {
        const uint32_t* WB = (const uint32_t*)W1Ks;
        #pragma unroll
        for (int ks = 0; ks < 8; ks++){
          float za1[4], zb1[4];
          {
            const float2 bpA = *(const float2*)(b1k + (2*ks)*8 + tg*2);
            const float2 bpB = *(const float2*)(b1k + (2*ks+1)*8 + tg*2);
            za1[0]=bpA.x; za1[1]=bpA.y; za1[2]=bpA.x; za1[3]=bpA.y;
            zb1[0]=bpB.x; zb1[1]=bpB.y; zb1[2]=bpB.x; zb1[3]=bpB.y;
          }
          {
            const int colA = (2*ks)*8 + g, colB = (2*ks+1)*8 + g;
            mma_tf32(za1, za, WB[tg*136 + colA], WB[(tg+4)*136 + colA]);
            mma_tf32(zb1, za, WB[tg*136 + colB], WB[(tg+4)*136 + colB]);
          }
          // af[ks][0]: h1[e=g][c=16ks+2tg..], [1]: e=8+g, [2]: c+8, [3]: both
          af[ks][0] = relu_pack(za1[0], za1[1]);
          af[ks][1] = relu_pack(za1[2], za1[3]);
          af[ks][2] = relu_pack(zb1[0], zb1[1]);
          af[ks][3] = relu_pack(zb1[2], zb1[3]);
        }
      }

      // ---- f-strips: z^T = W2(A) @ h1^T(B=af); agg = relu(z^T)(A) @ R^T(B) ----
      #pragma unroll 1
      for (int s = 0; s < 8; s++){
        // z^T rows f = s*16+g, +8; cols = warp's 16 edges (2 e-groups)
        float z0[4], z1[4];
        {
          const float bg0 = b2k[s*16 + g];
          const float bg1 = b2k[s*16 + 8 + g];
          z0[0]=bg0; z0[1]=bg0; z0[2]=bg1; z0[3]=bg1;
          z1[0]=bg0; z1[1]=bg0; z1[2]=bg1; z1[3]=bg1;
        }
        {
          const uint32_t wrow = wbase + (uint32_t)(s*16*272);
          #pragma unroll
          for (int ks = 0; ks < 8; ks++){
            uint32_t wf[4];
            ldsm4(wf, wrow + ks*32);
            mma16816(z0, wf[0],wf[1],wf[2],wf[3], af[ks][0], af[ks][2]);  // e 0-7
            mma16816(z1, wf[0],wf[1],wf[2],wf[3], af[ks][1], af[ks][3]);  // e 8-15
          }
        }
        // agg MMA: A = relu(z^T) [f][e] (K = 16 edges), B = R^T (bt)
        const uint32_t a0 = relu_pack(z0[0], z0[1]);
        const uint32_t a1 = relu_pack(z0[2], z0[3]);
        const uint32_t a2 = relu_pack(z1[0], z1[1]);
        const uint32_t a3 = relu_pack(z1[2], z1[3]);
        float cagg[2][4];
        #pragma unroll
        for (int ng = 0; ng < 2; ng++)
          #pragma unroll
          for (int r2 = 0; r2 < 4; r2++) cagg[ng][r2] = 0.f;
        mma16816(cagg[0], a0,a1,a2,a3, bt[0], bt[1]);   // nodes n0+0..7
        mma16816(cagg[1], a0,a1,a2,a3, bt[2], bt[3]);   // nodes n0+8..15
        // apply: C[f][node]; lane holds f = s*16+g (+8), nodes tg*2+{0,1}(+8)
        #pragma unroll
        for (int ii = 0; ii < 4; ii++){
          if ((tch >> ii) & 1){
            float* pp = prow[ii] + s*16;
            atomicAdd(pp,     cagg[ii >> 1][ii & 1]);
            atomicAdd(pp + 8, cagg[ii >> 1][(ii & 1) + 2]);
          }
        }
      }
    }
    __syncthreads();   // all reads of W2k/W1K/RTk done before restage / phase B
  }

  // ================= node MLP (weight-stationary, i-split halves) =========
  float* AUG = (float*)(smc + PB_AUG);   // [30][132]
  float* H   = (float*)(smc + PB_H);     // [30][128]
  float* H2  = (float*)(smc + PB_H2);    // [30][129] (over AUG, dead then)
  float* P0  = (float*)(smc + PB_P0);
  float* P1  = (float*)(smc + PB_P1);

  for (int idx = tid; idx < NN*132; idx += THREADS){
    int n = idx / 132, i = idx - n*132;
    AUG[idx] = (i < 4) ? XS[n*4 + i] : AGG[n*132 + (i - 4)];
  }
  __syncthreads();
  { // layer 1: P[half] = aug @ oW1 (i-range split)
    const int f = tid & 127, half = tid >> 7;
    const int i0 = half ? 66 : 0, i1 = half ? 132 : 66;
    float acc[NN];
    #pragma unroll
    for (int n = 0; n < NN; n++) acc[n] = 0.f;
    for (int i = i0; i < i1; i++){
      const float w = oW1[i*128 + f];
      #pragma unroll
      for (int n = 0; n < NN; n++) acc[n] += AUG[n*132 + i] * w;
    }
    float* P = half ? P1 : P0;
    #pragma unroll
    for (int n = 0; n < NN; n++) P[n*128 + f] = acc[n];
  }
  __syncthreads();
  for (int idx = tid; idx < NN*128; idx += THREADS)
    H[idx] = fmaxf(P0[idx] + P1[idx] + ob1s[idx & 127], 0.f);
  __syncthreads();
  { // layer 2
    const int f = tid & 127, half = tid >> 7;
    const int i0 = half ? 64 : 0, i1 = half ? 128 : 64;
    float acc[NN];
    #pragma unroll
    for (int n = 0; n < NN; n++) acc[n] = 0.f;
    for (int i = i0; i < i1; i++){
      const float w = oW2[i*128 + f];
      #pragma unroll
      for (int n = 0; n < NN; n++) acc[n] += H[n*128 + i] * w;
    }
    float* P = half ? P1 : P0;
    #pragma unroll
    for (int n = 0; n < NN; n++) P[n*128 + f] = acc[n];
  }
  __syncthreads();
  for (int idx = tid; idx < NN*128; idx += THREADS){
    int n = idx >> 7, f = idx & 127;
    H2[n*129 + f] = fmaxf(P0[idx] + P1[idx] + ob2s[f], 0.f);
  }
  __syncthreads();
  if (tid < NN*4){ // layer 3 + residual
    const int n = tid >> 2, d = tid & 3;
    float a = ob3s[d];
    #pragma unroll 8
    for (int j = 0; j < 128; j++) a += H2[n*129 + j] * oW3[j*4 + d];
    out[((b*NN + n)*TOUT + t)*4 + d] = XS[n*4 + d] + a;
  }
}

extern "C" void kernel_launch(void* const* d_in, const int* in_sizes, int n_in,
                              void* d_out, int out_size) {
  (void)in_sizes; (void)n_in; (void)out_size;
  const float* inputs   = (const float*)d_in[0];
  const float* rel_type = (const float*)d_in[1];
  const float* W1  = (const float*)d_in[4];
  const float* b1  = (const float*)d_in[5];
  const float* W2  = (const float*)d_in[6];
  const float* b2  = (const float*)d_in[7];
  const float* oW1 = (const float*)d_in[8];
  const float* ob1 = (const float*)d_in[9];
  const float* oW2 = (const float*)d_in[10];
  const float* ob2 = (const float*)d_in[11];
  const float* oW3 = (const float*)d_in[12];
  const float* ob3 = (const float*)d_in[13];
  float* out = (float*)d_out;

  prep_w2<<<256, 256>>>(W2);

  cudaFuncSetAttribute(nri_mma_kernel,
                       cudaFuncAttributeMaxDynamicSharedMemorySize, SMEM_BYTES);
  nri_mma_kernel<<<GRID, THREADS, SMEM_BYTES>>>(
      inputs, rel_type, W1, b1, b2, oW1, ob1, oW2, ob2, oW3, ob3, out);
}

// round 17
// speedup vs baseline: 1.4809x; 1.4809x over previous
#include <cuda_runtime.h>
#include <cuda_fp16.h>
#include <cstdint>

// NRI MLPDecoder: L1 = mma.m16n8k8.tf32 (A-frags straight from XS, C-frag ==
// L2 A-frag in-register), L2 = mma.m16n8k16.f16 (ldmatrix B), aggregation =
// HMMA with R matrix (rel_type folded; warp-exclusive feature slices, plain RMW).
// k-outer, 2 CTAs/SM, 2 barriers/tile. Based on the 503us R11 baseline.
// B=16,N=30,T=50(49 out),D=4,K=4,H=M=NH=128,E=870(pad 896 = 7x128).
// One CTA = one (b,t), 256 threads, grid 784. Warp w owns edge rows w*16..w*16+15.

typedef unsigned long long ull;

#define NB 16
#define NN 30
#define TFULL 50
#define TOUT 49
#define EDGES 870
#define NTILE 7
#define THREADS 256
#define GRID (NB*TOUT)

// ---------------- smem byte offsets (R11 map; SPRE region now a dead hole) ----
#define SA    0          // msgs fp16 [128][136] = 34816
#define SW2   34816      // W2k fp16 [128][136] = 34816
#define SW1K  75776      // W1k tf32 [8][136] = 4352
#define SB1   80128      // b1 f32 [4][128] = 2048
#define SB2   82176      // b2 f32 [4][128] = 2048
#define SRTK  84224      // rt_k f32 [896] = 3584
#define SR    87808      // R fp16 [16][136] = 4352 (stride 272B)
#define SAGG  92160      // agg f32 [30][132] = 15840
#define SXS   108000     // x f32 [32][4] = 512
#define SOB   108512     // ob1 512 + ob2 512 + ob3 16
#define SMEM_BYTES 109552

// phase-B aliases
#define PB_AUG  (SA)             // [30][132] f32
#define PB_H    (SA + 16384)     // [30][128] f32
#define PB_P0   (SW2)            // [30][128] f32
#define PB_P1   (SW2 + 16384)    // [30][128] f32
#define PB_H2   (SAGG)           // [30][129] f32 (15480 <= 15840)

__device__ __align__(16) __half g_W2h[4*128*136];  // W2^T fp16: [k][f][c_pad136]

// ---------------- helpers ----------------
__device__ __forceinline__ uint32_t smem_u32(const void* p){
  uint32_t a; asm("{ .reg .u64 t; cvta.to.shared.u64 t, %1; cvt.u32.u64 %0, t; }" : "=r"(a) : "l"(p));
  return a;
}
__device__ __forceinline__ void cp16(uint32_t dst, const void* src){
  asm volatile("cp.async.ca.shared.global [%0], [%1], 16;" :: "r"(dst), "l"(src));
}
__device__ __forceinline__ void cp_commit(){ asm volatile("cp.async.commit_group;" ::: "memory"); }
__device__ __forceinline__ void cp_wait0(){ asm volatile("cp.async.wait_group 0;" ::: "memory"); }
__device__ __forceinline__ float cvt_tf32(float x){
  float o; asm("cvt.rna.tf32.f32 %0, %1;" : "=f"(o) : "f"(x)); return o;
}
__device__ __forceinline__ void mma16816(float* c,
    uint32_t a0, uint32_t a1, uint32_t a2, uint32_t a3,
    uint32_t b0, uint32_t b1){
  asm volatile("mma.sync.aligned.m16n8k16.row.col.f32.f16.f16.f32 "
    "{%0,%1,%2,%3}, {%4,%5,%6,%7}, {%8,%9}, {%0,%1,%2,%3};"
    : "+f"(c[0]), "+f"(c[1]), "+f"(c[2]), "+f"(c[3])
    : "r"(a0), "r"(a1), "r"(a2), "r"(a3), "r"(b0), "r"(b1));
}
__device__ __forceinline__ void mma_tf32(float* c,
    const uint32_t* a, uint32_t b0, uint32_t b1){
  asm volatile("mma.sync.aligned.m16n8k8.row.col.f32.tf32.tf32.f32 "
    "{%0,%1,%2,%3}, {%4,%5,%6,%7}, {%8,%9}, {%0,%1,%2,%3};"
    : "+f"(c[0]), "+f"(c[1]), "+f"(c[2]), "+f"(c[3])
    : "r"(a[0]), "r"(a[1]), "r"(a[2]), "r"(a[3]), "r"(b0), "r"(b1));
}
__device__ __forceinline__ void ldsm4(uint32_t* r, uint32_t addr){
  asm volatile("ldmatrix.sync.aligned.m8n8.x4.shared.b16 {%0,%1,%2,%3}, [%4];"
    : "=r"(r[0]), "=r"(r[1]), "=r"(r[2]), "=r"(r[3]) : "r"(addr));
}
__device__ __forceinline__ void ldsm4t(uint32_t* r, uint32_t addr){
  asm volatile("ldmatrix.sync.aligned.m8n8.x4.trans.shared.b16 {%0,%1,%2,%3}, [%4];"
    : "=r"(r[0]), "=r"(r[1]), "=r"(r[2]), "=r"(r[3]) : "r"(addr));
}
__device__ __forceinline__ uint32_t relu_pack(float a, float b){
  __half2 h = __floats2half2_rn(a, b);
  __half2 z = __half2half2(__ushort_as_half(0));
  __half2 r = __hmax2(h, z);
  return *(uint32_t*)&r;
}

// ---------------- prep: W2^T -> fp16, padded stride 136 ----------------
__global__ void prep_w2(const float* __restrict__ W2){
  int idx = blockIdx.x * blockDim.x + threadIdx.x;
  if (idx >= 4*128*128) return;
  int k = idx >> 14, rem = idx & 16383;
  int m = rem >> 7, c = rem & 127;
  g_W2h[(k*128 + m)*136 + c] = __float2half(W2[(k*128 + c)*128 + m]);
}

// ---------------- main ----------------
extern __shared__ __align__(16) char smc[];

__global__ __launch_bounds__(THREADS, 2)
void nri_mma_kernel(
    const float* __restrict__ inputs,    // [16,30,50,4]
    const float* __restrict__ rel_type,  // [16,870,4]
    const float* __restrict__ W1,        // [4,8,128]
    const float* __restrict__ b1,        // [4,128]
    const float* __restrict__ b2,        // [4,128]
    const float* __restrict__ oW1,       // [132,128]
    const float* __restrict__ ob1,
    const float* __restrict__ oW2,       // [128,128]
    const float* __restrict__ ob2,
    const float* __restrict__ oW3,       // [128,4]
    const float* __restrict__ ob3,
    float* __restrict__ out)             // [16,30,49,4]
{
  const int tid  = threadIdx.x;
  const int lane = tid & 31;
  const int g    = lane >> 2;      // groupID
  const int tg   = lane & 3;       // thread in group
  const int wid  = tid >> 5;       // warp: rows wid*16..wid*16+15 / feat slice wid*16
  const int qq   = lane >> 3;      // ldmatrix quad
  const int rr   = lane & 7;
  const int b = blockIdx.x / TOUT;
  const int t = blockIdx.x % TOUT;

  const uint32_t sbase = smem_u32(smc);
  float* W1Ks = (float*)(smc + SW1K);
  float* b1s  = (float*)(smc + SB1);
  float* b2s  = (float*)(smc + SB2);
  float* RTk  = (float*)(smc + SRTK);
  float* AGG  = (float*)(smc + SAGG);
  float* XS   = (float*)(smc + SXS);
  float* ob1s = (float*)(smc + SOB);
  float* ob2s = (float*)(smc + SOB + 512);
  float* ob3s = (float*)(smc + SOB + 1024);

  // ---- prologue ----
  for (int i = tid; i < 128; i += THREADS){
    cp16(sbase + SB1 + i*16, (const char*)b1 + i*16);
    cp16(sbase + SB2 + i*16, (const char*)b2 + i*16);
  }
  cp_commit();
  if (tid < 120){
    int n = tid >> 2, d = tid & 3;
    XS[tid] = inputs[((b*NN + n)*TFULL + t)*4 + d];
  }
  for (int i = tid; i < NN*132; i += THREADS) AGG[i] = 0.f;
  if (tid < 128) ob1s[tid] = ob1[tid];
  else           ob2s[tid-128] = ob2[tid-128];
  if (tid < 4) ob3s[tid] = ob3[tid];
  cp_wait0();

  // ================= relation types (outer) =================
  for (int k = 0; k < 4; k++){
    // ---- stage W2k (fp16), W1k (tf32), rt_k ----
    for (int i = tid; i < 2176; i += THREADS)
      cp16(sbase + SW2 + i*16, (const char*)g_W2h + k*34816 + i*16);
    cp_commit();
    for (int i = tid; i < 1024; i += THREADS)
      W1Ks[(i >> 7)*136 + (i & 127)] = cvt_tf32(W1[k*1024 + i]);
    for (int i = tid; i < 896; i += THREADS)
      RTk[i] = (i < EDGES) ? rel_type[(b*EDGES + i)*4 + k] : 0.f;
    cp_wait0();
    __syncthreads();

    const float* b1k = b1s + k*128;
    const float* b2k = b2s + k*128;

    // ---- edge tiles ----
    for (int m = 0; m < NTILE; m++){
      const int gbase = m*128;
      const int n0 = (gbase*565) >> 14;

      // ---- build R fp16 [16][136]: R[row][e] = rt iff recv==n0+row ----
      // (read in agg phase only, which sits behind s2; tile-to-tile reuse
      //  protected by s3 — no dedicated barrier needed.)
      #pragma unroll
      for (int it = 0; it < 4; it++){
        const int idx = tid + it*256;        // 1024 half2 entries
        const int row = idx >> 6, pr = idx & 63;
        const int e = pr*2, geA = gbase + e;
        const int nA = (geA*565) >> 14, nB = ((geA+1)*565) >> 14;
        const float vA = (nA == n0 + row) ? RTk[geA] : 0.f;
        const float vB = (nB == n0 + row) ? RTk[geA+1] : 0.f;
        *(__half2*)(smc + SR + row*272 + e*2) = __floats2half2_rn(vA, vB);
      }

      // ---- layer-1 A-frags straight from XS (no PRE buffer) ----
      // pad edges (ge>=EDGES) read node 0 — harmless: their msgs are
      // annihilated exactly by R's zero columns, AGG is bit-identical.
      uint32_t za[4];
      {
        const int ea = gbase + wid*16 + g, eb = ea + 8;
        int na = 0, sa = 0, nb = 0, sb = 0;
        if (ea < EDGES){ na = (ea*565) >> 14; int ix = ea - na*29; sa = ix + (ix >= na); }
        if (eb < EDGES){ nb = (eb*565) >> 14; int ix = eb - nb*29; sb = ix + (ix >= nb); }
        za[0] = __float_as_uint(cvt_tf32(XS[na*4 + tg]));   // (row g,   col tg)   recv
        za[1] = __float_as_uint(cvt_tf32(XS[nb*4 + tg]));   // (row 8+g, col tg)   recv
        za[2] = __float_as_uint(cvt_tf32(XS[sa*4 + tg]));   // (row g,   col 4+tg) send
        za[3] = __float_as_uint(cvt_tf32(XS[sb*4 + tg]));   // (row 8+g, col 4+tg) send
      }

      // ---- layer 1: tf32 MMA -> relu -> A-frags in registers ----
      uint32_t af[8][4];
      {
        const uint32_t* WB = (const uint32_t*)W1Ks;
        #pragma unroll
        for (int ks = 0; ks < 8; ks++){
          float za1[4], zb1[4];
          {
            const float2 bpA = *(const float2*)(b1k + (2*ks)*8 + tg*2);
            const float2 bpB = *(const float2*)(b1k + (2*ks+1)*8 + tg*2);
            za1[0]=bpA.x; za1[1]=bpA.y; za1[2]=bpA.x; za1[3]=bpA.y;
            zb1[0]=bpB.x; zb1[1]=bpB.y; zb1[2]=bpB.x; zb1[3]=bpB.y;
          }
          {
            const int colA = (2*ks)*8 + g, colB = (2*ks+1)*8 + g;
            mma_tf32(za1, za, WB[tg*136 + colA], WB[(tg+4)*136 + colA]);
            mma_tf32(zb1, za, WB[tg*136 + colB], WB[(tg+4)*136 + colB]);
          }
          af[ks][0] = relu_pack(za1[0], za1[1]);
          af[ks][1] = relu_pack(za1[2], za1[3]);
          af[ks][2] = relu_pack(zb1[0], zb1[1]);
          af[ks][3] = relu_pack(zb1[2], zb1[3]);
        }
      }

      // ---- layer 2: two N-halves; msgs = relu(z + b2) -> SA ----
      const int rlo = wid*16 + g, rhi = rlo + 8;
      #pragma unroll
      for (int h2 = 0; h2 < 2; h2++){
        const int fb = h2*64;
        float z[8][4];
        #pragma unroll
        for (int j = 0; j < 8; j++){
          const float2 bp = *(const float2*)(b2k + fb + j*8 + tg*2);
          z[j][0]=bp.x; z[j][1]=bp.y; z[j][2]=bp.x; z[j][3]=bp.y;
        }
        #pragma unroll
        for (int ks = 0; ks < 8; ks++){
          uint32_t bq[4][4];
          #pragma unroll
          for (int jp = 0; jp < 4; jp++)
            ldsm4(bq[jp], sbase + SW2 +
              ((h2*8 + jp*2 + (qq >> 1))*8 + rr)*272 + (qq & 1)*16 + ks*32);
          #pragma unroll
          for (int jp = 0; jp < 4; jp++){
            mma16816(z[2*jp],   af[ks][0],af[ks][1],af[ks][2],af[ks][3], bq[jp][0], bq[jp][1]);
            mma16816(z[2*jp+1], af[ks][0],af[ks][1],af[ks][2],af[ks][3], bq[jp][2], bq[jp][3]);
          }
        }
        #pragma unroll
        for (int j = 0; j < 8; j++){
          const int f = fb + j*8 + tg*2;
          *(uint32_t*)(smc + SA + rlo*272 + f*2) = relu_pack(z[j][0], z[j][1]);
          *(uint32_t*)(smc + SA + rhi*272 + f*2) = relu_pack(z[j][2], z[j][3]);
        }
      }
      __syncthreads();   // s2: all msgs + R visible

      // ---- aggregation MMA: C[16 nodes][16 feat] = R @ msgs ----
      {
        const int f0 = wid*16;
        float cagg[2][4];
        #pragma unroll
        for (int j = 0; j < 2; j++)
          #pragma unroll
          for (int r2 = 0; r2 < 4; r2++) cagg[j][r2] = 0.f;
        const uint32_t Ra = sbase + SR + ((qq & 1)*8 + rr)*272 + (qq >> 1)*16;
        const uint32_t Ba = sbase + SA + ((qq & 1)*8 + rr)*272 + (f0 + (qq >> 1)*8)*2;
        #pragma unroll
        for (int ks = 0; ks < 8; ks++){
          uint32_t ar[4], br[4];
          ldsm4(ar, Ra + ks*32);
          ldsm4t(br, Ba + ks*16*272);
          mma16816(cagg[0], ar[0],ar[1],ar[2],ar[3], br[0], br[1]);
          mma16816(cagg[1], ar[0],ar[1],ar[2],ar[3], br[2], br[3]);
        }
        const int row0 = n0 + g, row1 = n0 + 8 + g;
        if (row0 < NN){
          #pragma unroll
          for (int j = 0; j < 2; j++){
            float2* p = (float2*)(AGG + row0*132 + f0 + j*8 + tg*2);
            float2 c = *p; c.x += cagg[j][0]; c.y += cagg[j][1]; *p = c;
          }
        }
        if (row1 < NN){
          #pragma unroll
          for (int j = 0; j < 2; j++){
            float2* p = (float2*)(AGG + row1*132 + f0 + j*8 + tg*2);
            float2 c = *p; c.x += cagg[j][2]; c.y += cagg[j][3]; *p = c;
          }
        }
      }
      __syncthreads();   // s3: agg done before R/msgs overwrite next tile
    }
  }

  // ================= node MLP (weight-stationary, i-split halves) =========
  float* AUG = (float*)(smc + PB_AUG);   // [30][132]
  float* H   = (float*)(smc + PB_H);     // [30][128]
  float* H2  = (float*)(smc + PB_H2);    // [30][129]
  float* P0  = (float*)(smc + PB_P0);
  float* P1  = (float*)(smc + PB_P1);

  for (int idx = tid; idx < NN*132; idx += THREADS){
    int n = idx / 132, i = idx - n*132;
    AUG[idx] = (i < 4) ? XS[n*4 + i] : AGG[n*132 + (i - 4)];
  }
  __syncthreads();
  { // layer 1: P[half] = aug @ oW1 (i-range split)
    const int f = tid & 127, half = tid >> 7;
    const int i0 = half ? 66 : 0, i1 = half ? 132 : 66;
    float acc[NN];
    #pragma unroll
    for (int n = 0; n < NN; n++) acc[n] = 0.f;
    for (int i = i0; i < i1; i++){
      const float w = oW1[i*128 + f];
      #pragma unroll
      for (int n = 0; n < NN; n++) acc[n] += AUG[n*132 + i] * w;
    }
    float* P = half ? P1 : P0;
    #pragma unroll
    for (int n = 0; n < NN; n++) P[n*128 + f] = acc[n];
  }
  __syncthreads();
  for (int idx = tid; idx < NN*128; idx += THREADS)
    H[idx] = fmaxf(P0[idx] + P1[idx] + ob1s[idx & 127], 0.f);
  __syncthreads();
  { // layer 2
    const int f = tid & 127, half = tid >> 7;
    const int i0 = half ? 64 : 0, i1 = half ? 128 : 64;
    float acc[NN];
    #pragma unroll
    for (int n = 0; n < NN; n++) acc[n] = 0.f;
    for (int i = i0; i < i1; i++){
      const float w = oW2[i*128 + f];
      #pragma unroll
      for (int n = 0; n < NN; n++) acc[n] += H[n*128 + i] * w;
    }
    float* P = half ? P1 : P0;
    #pragma unroll
    for (int n = 0; n < NN; n++) P[n*128 + f] = acc[n];
  }
  __syncthreads();
  for (int idx = tid; idx < NN*128; idx += THREADS){
    int n = idx >> 7, f = idx & 127;
    H2[n*129 + f] = fmaxf(P0[idx] + P1[idx] + ob2s[f], 0.f);
  }
  __syncthreads();
  if (tid < NN*4){ // layer 3 + residual
    const int n = tid >> 2, d = tid & 3;
    float a = ob3s[d];
    #pragma unroll 8
    for (int j = 0; j < 128; j++) a += H2[n*129 + j] * oW3[j*4 + d];
    out[((b*NN + n)*TOUT + t)*4 + d] = XS[n*4 + d] + a;
  }
}

extern "C" void kernel_launch(void* const* d_in, const int* in_sizes, int n_in,
                              void* d_out, int out_size) {
  (void)in_sizes; (void)n_in; (void)out_size;
  const float* inputs   = (const float*)d_in[0];
  const float* rel_type = (const float*)d_in[1];
  const float* W1  = (const float*)d_in[4];
  const float* b1  = (const float*)d_in[5];
  const float* W2  = (const float*)d_in[6];
  const float* b2  = (const float*)d_in[7];
  const float* oW1 = (const float*)d_in[8];
  const float* ob1 = (const float*)d_in[9];
  const float* oW2 = (const float*)d_in[10];
  const float* ob2 = (const float*)d_in[11];
  const float* oW3 = (const float*)d_in[12];
  const float* ob3 = (const float*)d_in[13];
  float* out = (float*)d_out;

  prep_w2<<<256, 256>>>(W2);

  cudaFuncSetAttribute(nri_mma_kernel,
                       cudaFuncAttributeMaxDynamicSharedMemorySize, SMEM_BYTES);
  nri_mma_kernel<<<GRID, THREADS, SMEM_BYTES>>>(
      inputs, rel_type, W1, b1, b2, oW1, ob1, oW2, ob2, oW3, ob3, out);
}